// round 10
// baseline (speedup 1.0000x reference)
#include <cuda_runtime.h>
#include <cuda_bf16.h>
#include <cstdint>

// ---------------- problem dims ----------------
#define TT 1024
#define BB 8
#define DD 1024
#define HH 16
#define ROWS 8192
#define SEGC 8388608u
#define KC 3072                 // concatenated split-bf16 K (hi|hi|lo vs hi|lo|hi)

typedef unsigned long long ull;

// ---------------- device scratch ----------------
__device__ float g_proj[5ull * SEGC];     // q,k,v,apre,bpre (fp32)
__device__ float g_alpha[ROWS * HH];
__device__ float g_beta[ROWS * HH];
__device__ __align__(16) __nv_bfloat16 g_xcat[(size_t)ROWS * KC];   // 48 MB
__device__ __align__(16) __nv_bfloat16 g_wcat[(size_t)5120 * KC];   // 30 MB

// ---------------- helpers ----------------
__device__ __forceinline__ uint32_t smem_u32(const void* p) {
    uint32_t a;
    asm("{ .reg .u64 t; cvta.to.shared.u64 t, %1; cvt.u32.u64 %0, t; }" : "=r"(a) : "l"(p));
    return a;
}
__device__ __forceinline__ void cpa16(uint32_t dst, const void* src) {
    asm volatile("cp.async.cg.shared.global [%0], [%1], 16;" :: "r"(dst), "l"(src));
}
#define CP_COMMIT() asm volatile("cp.async.commit_group;")
#define CP_WAIT2()  asm volatile("cp.async.wait_group 2;")

__device__ __forceinline__ void ldm4(uint32_t* r, uint32_t a) {
    asm volatile("ldmatrix.sync.aligned.m8n8.x4.shared.b16 {%0,%1,%2,%3}, [%4];"
        : "=r"(r[0]), "=r"(r[1]), "=r"(r[2]), "=r"(r[3]) : "r"(a));
}
__device__ __forceinline__ void mma16816(float* d, const uint32_t* a, uint32_t b0, uint32_t b1) {
    asm volatile(
        "mma.sync.aligned.m16n8k16.row.col.f32.bf16.bf16.f32 "
        "{%0,%1,%2,%3},{%4,%5,%6,%7},{%8,%9},{%0,%1,%2,%3};"
        : "+f"(d[0]), "+f"(d[1]), "+f"(d[2]), "+f"(d[3])
        : "r"(a[0]), "r"(a[1]), "r"(a[2]), "r"(a[3]), "r"(b0), "r"(b1));
}

// packed f32x2 (sm_100+ FFMA2)
#define FMA2(d, a, b, c) asm("fma.rn.f32x2 %0, %1, %2, %3;" : "=l"(d) : "l"(a), "l"(b), "l"(c))
#define MUL2(d, a, b)    asm("mul.rn.f32x2 %0, %1, %2;"     : "=l"(d) : "l"(a), "l"(b))
#define PK2(d, x, y)     asm("mov.b64 %0, {%1, %2};"        : "=l"(d) : "f"(x), "f"(y))
#define UNPK2(x, y, d)   asm("mov.b64 {%0, %1}, %2;"        : "=f"(x), "=f"(y) : "l"(d))

// split one float into bf16 hi + bf16 lo
__device__ __forceinline__ void split2(float f0, float f1, uint32_t& hw, uint32_t& lw) {
    __nv_bfloat16 h0 = __float2bfloat16(f0);
    __nv_bfloat16 h1 = __float2bfloat16(f1);
    __nv_bfloat16 l0 = __float2bfloat16(f0 - __bfloat162float(h0));
    __nv_bfloat16 l1 = __float2bfloat16(f1 - __bfloat162float(h1));
    hw = (uint32_t)__bfloat16_as_ushort(h0) | ((uint32_t)__bfloat16_as_ushort(h1) << 16);
    lw = (uint32_t)__bfloat16_as_ushort(l0) | ((uint32_t)__bfloat16_as_ushort(l1) << 16);
}

// =====================================================================
// pack_all: fused pack_x + pack_w.
// =====================================================================
__global__ __launch_bounds__(256)
void pack_all(const float* __restrict__ x,
              const float* __restrict__ W0, const float* __restrict__ W1,
              const float* __restrict__ W2, const float* __restrict__ W3,
              const float* __restrict__ W4)
{
    unsigned idx = blockIdx.x * 256 + threadIdx.x;
    if (idx < 1048576u) {
        unsigned e = idx * 8;
        unsigned row = e >> 10, col = e & 1023;
        float4 f0 = *(const float4*)(x + e);
        float4 f1 = *(const float4*)(x + e + 4);
        uint4 hi, lo;
        split2(f0.x, f0.y, hi.x, lo.x);
        split2(f0.z, f0.w, hi.y, lo.y);
        split2(f1.x, f1.y, hi.z, lo.z);
        split2(f1.z, f1.w, hi.w, lo.w);
        __nv_bfloat16* base = g_xcat + (size_t)row * KC;
        *(uint4*)(base + col)        = hi;
        *(uint4*)(base + col + 1024) = hi;
        *(uint4*)(base + col + 2048) = lo;
    } else {
        unsigned j = idx - 1048576u;
        unsigned e = j * 8;
        unsigned seg = e >> 20;
        unsigned n = (e >> 10) & 1023, k = e & 1023;
        const float* W = (seg == 0) ? W0 : (seg == 1) ? W1 : (seg == 2) ? W2
                         : (seg == 3) ? W3 : W4;
        const float* src = W + (size_t)n * 1024 + k;
        float4 f0 = *(const float4*)(src);
        float4 f1 = *(const float4*)(src + 4);
        uint4 hi, lo;
        split2(f0.x, f0.y, hi.x, lo.x);
        split2(f0.z, f0.w, hi.y, lo.y);
        split2(f1.x, f1.y, hi.z, lo.z);
        split2(f1.z, f1.w, hi.w, lo.w);
        __nv_bfloat16* base = g_wcat + (size_t)(seg * 1024 + n) * KC;
        *(uint4*)(base + k)        = hi;
        *(uint4*)(base + k + 1024) = lo;
        *(uint4*)(base + k + 2048) = hi;
    }
}

// =====================================================================
// gemm_mma: unchanged R8 config (best measured: 752.9us, tensor 56.6%).
// =====================================================================
#define STG 20480

__global__ __launch_bounds__(256, 2)
void gemm_mma()
{
    extern __shared__ __align__(16) unsigned char sm[];
    const uint32_t smb = smem_u32(sm);

    const int bid = blockIdx.x;
    const int mt = bid / 40, nt = bid % 40;
    const int tid = threadIdx.x;
    const int lane = tid & 31, wid = tid >> 5;
    const int wm = wid & 1, wn = wid >> 1;

    const int lrow = tid >> 2, lch = tid & 3;
    const __nv_bfloat16* Ag = g_xcat + (size_t)(mt * 128 + lrow) * KC + lch * 8;
    const __nv_bfloat16* Bg = g_wcat + (size_t)(nt * 128 + lrow) * KC + lch * 8;
    const uint32_t sA = smb + lrow * 80 + lch * 16;
    const uint32_t sB = smb + 10240 + lrow * 80 + lch * 16;

    auto load = [&](int it, int stage) {
        const uint32_t off = stage * STG;
        const __nv_bfloat16* ag = Ag + it * 32;
        const __nv_bfloat16* bg = Bg + it * 32;
        cpa16(sA + off,           ag);
        cpa16(sA + off + 64 * 80, ag + (size_t)64 * KC);
        cpa16(sB + off,           bg);
        cpa16(sB + off + 64 * 80, bg + (size_t)64 * KC);
    };

    uint32_t aAddr[4], bAddr[2];
#pragma unroll
    for (int f = 0; f < 4; f++)
        aAddr[f] = smb + (wm * 64 + f * 16 + (lane & 15)) * 80 + (lane >> 4) * 16;
#pragma unroll
    for (int x = 0; x < 2; x++)
        bAddr[x] = smb + 10240 + (wn * 32 + x * 16 + (lane & 15)) * 80 + (lane >> 4) * 16;

    float acc[4][4][4];
#pragma unroll
    for (int f = 0; f < 4; f++)
#pragma unroll
        for (int g = 0; g < 4; g++)
#pragma unroll
            for (int i = 0; i < 4; i++) acc[f][g][i] = 0.f;

    load(0, 0); CP_COMMIT();
    load(1, 1); CP_COMMIT();
    load(2, 2); CP_COMMIT();

    const int NIT = KC / 32;    // 96
    for (int it = 0; it < NIT; it++) {
        CP_WAIT2();
        __syncthreads();
        if (it + 3 < NIT) load(it + 3, (it + 3) & 3);
        CP_COMMIT();

        const uint32_t st = (it & 3) * STG;
#pragma unroll
        for (int ks = 0; ks < 2; ks++) {
            uint32_t af[4][4], bf[2][4];
#pragma unroll
            for (int f = 0; f < 4; f++) ldm4(af[f], aAddr[f] + st + ks * 32);
#pragma unroll
            for (int x = 0; x < 2; x++) ldm4(bf[x], bAddr[x] + st + ks * 32);
#pragma unroll
            for (int f = 0; f < 4; f++) {
#pragma unroll
                for (int g = 0; g < 4; g++) {
                    const uint32_t b0 = bf[g >> 1][g & 1];
                    const uint32_t b1 = bf[g >> 1][(g & 1) + 2];
                    mma16816(acc[f][g], af[f], b0, b1);
                }
            }
        }
    }

    const int seg = nt >> 3;
    float* op = g_proj + (size_t)seg * SEGC;
    const int rbase = mt * 128 + wm * 64 + (lane >> 2);
    const int cbase = (nt & 7) * 128 + wn * 32 + (lane & 3) * 2;
#pragma unroll
    for (int f = 0; f < 4; f++) {
#pragma unroll
        for (int g = 0; g < 4; g++) {
            const int r = rbase + f * 16;
            const int c = cbase + g * 8;
            float2 v0 = make_float2(acc[f][g][0], acc[f][g][1]);
            float2 v1 = make_float2(acc[f][g][2], acc[f][g][3]);
            *(float2*)(op + (size_t)r * 1024 + c)       = v0;
            *(float2*)(op + (size_t)(r + 8) * 1024 + c) = v1;
        }
    }
}

// =====================================================================
// postproc: unchanged.
// =====================================================================
__device__ __forceinline__ float sigf(float x) { return 1.0f / (1.0f + expf(-x)); }

__global__ __launch_bounds__(256)
void postproc(const float* __restrict__ b_alpha, const float* __restrict__ b_beta)
{
    const int wid = threadIdx.x >> 5;
    const int lane = threadIdx.x & 31;
    const int gb = blockIdx.x * 8 + wid;   // tb*16 + h
    const int h = gb & 15;
    const size_t row = (size_t)(gb >> 4) * DD + h * 64 + lane * 2;

    float2 q  = *(float2*)(g_proj + row);
    float2 k  = *(float2*)(g_proj + (size_t)SEGC + row);
    float2 ap = *(float2*)(g_proj + 3ull * SEGC + row);
    float2 bp = *(float2*)(g_proj + 4ull * SEGC + row);
    float2 ba = *(const float2*)(b_alpha + h * 64 + lane * 2);
    float2 bbv = *(const float2*)(b_beta + h * 64 + lane * 2);

    float sq = fmaf(q.x, q.x, q.y * q.y);
    float sk = fmaf(k.x, k.x, k.y * k.y);
    float sa = sigf(ap.x + ba.x) + sigf(ap.y + ba.y);
    float sb = sigf(bp.x + bbv.x) + sigf(bp.y + bbv.y);
#pragma unroll
    for (int m = 16; m; m >>= 1) {
        sq += __shfl_xor_sync(0xffffffffu, sq, m);
        sk += __shfl_xor_sync(0xffffffffu, sk, m);
        sa += __shfl_xor_sync(0xffffffffu, sa, m);
        sb += __shfl_xor_sync(0xffffffffu, sb, m);
    }
    const float qi = 1.0f / fmaxf(sqrtf(sq), 1e-12f);
    const float ki = 1.0f / fmaxf(sqrtf(sk), 1e-12f);
    q.x *= qi; q.y *= qi;
    k.x *= ki; k.y *= ki;
    *(float2*)(g_proj + row) = q;
    *(float2*)(g_proj + (size_t)SEGC + row) = k;
    if (lane == 0) {
        g_alpha[gb] = sa * (1.0f / 64.0f);
        g_beta[gb]  = sb * (1.0f / 64.0f);
    }
}

// =====================================================================
// scan v4: 128 blocks x 128 threads (4 warps = 1/SMSP).
// Thread (row d = wid*16 + lane>>1, half e = lane&1) owns S[d][e*32..+32)
// as 16 f32x2 pairs. Only 2 shfls/step; k/q loaded as ulonglong2 (no
// PK2 movs). Prefetch distance 2 (double-buffered in registers).
// =====================================================================
struct ScanSlot {
    ull K[16];
    ull Q[16];
    float v, a, b;
};

__device__ __forceinline__ void scan_load(ScanSlot& s, int t,
                                          const float* kb, const float* qb,
                                          const float* vb, int bh)
{
    const ulonglong2* kp = (const ulonglong2*)(kb + (size_t)t * 8192);
    const ulonglong2* qp = (const ulonglong2*)(qb + (size_t)t * 8192);
#pragma unroll
    for (int i = 0; i < 8; i++) { ulonglong2 tv = kp[i]; s.K[2*i] = tv.x; s.K[2*i+1] = tv.y; }
#pragma unroll
    for (int i = 0; i < 8; i++) { ulonglong2 tv = qp[i]; s.Q[2*i] = tv.x; s.Q[2*i+1] = tv.y; }
    s.v = vb[(size_t)t * 8192];
    s.a = g_alpha[t * 128 + bh];
    s.b = g_beta[t * 128 + bh];
}

__device__ __forceinline__ void scan_step(ScanSlot& sl, ull (&S)[16],
                                          int t, int e, float* out, size_t ob)
{
    const float a = sl.a, be = sl.b, vv = sl.v;

    // dot: sk_partial = S . k  (4 independent chains)
    ull d0, d1, d2, d3;
    MUL2(d0, S[0], sl.K[0]); MUL2(d1, S[1], sl.K[1]);
    MUL2(d2, S[2], sl.K[2]); MUL2(d3, S[3], sl.K[3]);
#pragma unroll
    for (int j = 4; j < 16; j += 4) {
        FMA2(d0, S[j],   sl.K[j],   d0);
        FMA2(d1, S[j+1], sl.K[j+1], d1);
        FMA2(d2, S[j+2], sl.K[j+2], d2);
        FMA2(d3, S[j+3], sl.K[j+3], d3);
    }
    float p0, p1, p2, p3, p4, p5, p6, p7;
    UNPK2(p0, p1, d0); UNPK2(p2, p3, d1);
    UNPK2(p4, p5, d2); UNPK2(p6, p7, d3);
    float sk = ((p0 + p1) + (p2 + p3)) + ((p4 + p5) + (p6 + p7));
    sk += __shfl_xor_sync(0xffffffffu, sk, 1);

    const float coef = be * fmaf(-a, sk, vv);
    ull a2, c2;
    PK2(a2, a, a); PK2(c2, coef, coef);

    // update + output dot
    ull o0, o1, o2, o3, tmp;
    MUL2(tmp, a2, S[0]); FMA2(S[0], c2, sl.K[0], tmp); MUL2(o0, S[0], sl.Q[0]);
    MUL2(tmp, a2, S[1]); FMA2(S[1], c2, sl.K[1], tmp); MUL2(o1, S[1], sl.Q[1]);
    MUL2(tmp, a2, S[2]); FMA2(S[2], c2, sl.K[2], tmp); MUL2(o2, S[2], sl.Q[2]);
    MUL2(tmp, a2, S[3]); FMA2(S[3], c2, sl.K[3], tmp); MUL2(o3, S[3], sl.Q[3]);
#pragma unroll
    for (int j = 4; j < 16; j += 4) {
        MUL2(tmp, a2, S[j]);   FMA2(S[j],   c2, sl.K[j],   tmp); FMA2(o0, S[j],   sl.Q[j],   o0);
        MUL2(tmp, a2, S[j+1]); FMA2(S[j+1], c2, sl.K[j+1], tmp); FMA2(o1, S[j+1], sl.Q[j+1], o1);
        MUL2(tmp, a2, S[j+2]); FMA2(S[j+2], c2, sl.K[j+2], tmp); FMA2(o2, S[j+2], sl.Q[j+2], o2);
        MUL2(tmp, a2, S[j+3]); FMA2(S[j+3], c2, sl.K[j+3], tmp); FMA2(o3, S[j+3], sl.Q[j+3], o3);
    }
    float q0, q1, q2, q3, q4, q5, q6, q7;
    UNPK2(q0, q1, o0); UNPK2(q2, q3, o1);
    UNPK2(q4, q5, o2); UNPK2(q6, q7, o3);
    float oo = ((q0 + q1) + (q2 + q3)) + ((q4 + q5) + (q6 + q7));
    oo += __shfl_xor_sync(0xffffffffu, oo, 1);
    if (e == 0) out[(size_t)t * 8192 + ob] = oo;
}

__global__ __launch_bounds__(128, 1)
void scan(const float* __restrict__ S0, float* __restrict__ out)
{
    const int bh = blockIdx.x;
    const int b = bh >> 4, h = bh & 15;
    const int tid = threadIdx.x;
    const int lane = tid & 31, wid = tid >> 5;
    const int r = wid * 16 + (lane >> 1);   // row d: 0..63
    const int e = lane & 1;                 // half: elements [e*32, e*32+32)

    // state: 16 f32x2 pairs
    ull S[16];
    const ulonglong2* Sp = (const ulonglong2*)(S0 + ((size_t)bh * 64 + r) * 64 + e * 32);
#pragma unroll
    for (int i = 0; i < 8; i++) { ulonglong2 tv = Sp[i]; S[2*i] = tv.x; S[2*i+1] = tv.y; }

    const size_t base = (size_t)b * DD + h * 64;
    const float* qb = g_proj + base + e * 32;
    const float* kb = g_proj + (size_t)SEGC + base + e * 32;
    const float* vb = g_proj + 2ull * SEGC + base + r;
    const size_t ob = base + r;

    ScanSlot s0, s1;
    scan_load(s0, 0, kb, qb, vb, bh);
    scan_load(s1, 1, kb, qb, vb, bh);

    for (int t = 0; t < TT; t += 2) {
        scan_step(s0, S, t, e, out, ob);
        if (t + 2 < TT) scan_load(s0, t + 2, kb, qb, vb, bh);
        scan_step(s1, S, t + 1, e, out, ob);
        if (t + 3 < TT) scan_load(s1, t + 3, kb, qb, vb, bh);
    }

    // final state -> d_out tail region (B,H,DH,DH)
    ulonglong2* So = (ulonglong2*)(out + (size_t)(TT * BB * DD) + ((size_t)bh * 64 + r) * 64 + e * 32);
#pragma unroll
    for (int i = 0; i < 8; i++) So[i] = make_ulonglong2(S[2*i], S[2*i+1]);
}

// =====================================================================
extern "C" void kernel_launch(void* const* d_in, const int* in_sizes, int n_in,
                              void* d_out, int out_size)
{
    const float* x  = (const float*)d_in[0];
    const float* S0 = (const float*)d_in[1];
    const float* Wq = (const float*)d_in[2];
    const float* Wk = (const float*)d_in[3];
    const float* Wv = (const float*)d_in[4];
    const float* Wa = (const float*)d_in[5];
    const float* ba = (const float*)d_in[6];
    const float* Wb = (const float*)d_in[7];
    const float* bb = (const float*)d_in[8];
    float* out = (float*)d_out;

    cudaFuncSetAttribute(gemm_mma, cudaFuncAttributeMaxDynamicSharedMemorySize, 4 * STG);

    pack_all<<<6656, 256>>>(x, Wq, Wk, Wv, Wa, Wb);
    gemm_mma<<<2560, 256, 4 * STG>>>();
    postproc<<<16384, 256>>>(ba, bb);
    scan<<<BB * HH, 128>>>(S0, out);   // 4th launch -> ncu capture slot
}